// round 11
// baseline (speedup 1.0000x reference)
#include <cuda_runtime.h>
#include <cuda_bf16.h>

// Inverse db1 DWT (Haar), grouped transposed conv 2x2 stride 2 — no overlap.
// x: (16, 128, 128, 128) f32; inv_filters: (2,2,2) f32
// out: (16, 64, 256, 256) f32
//
// out[b,g,2h+i,2w+j] = x[b,2g,h,w]*f0[i,j] + x[b,2g+1,h,w]*f1[i,j]
//
// R10: R3 mapping (bench-best; every load/store individually warp-dense)
// with an L2-retention-aware cache policy for the graph-replay steady state:
//   - loads: default caching (__ldg) — input is 128 MiB ≈ L2 size; keep it
//     resident across replays so steady-state DRAM reads mostly disappear.
//   - stores: __stcs (evict-first) — the 256 MiB write stream must NOT evict
//     the read set; stream it straight through L2.

static constexpr int B  = 16;
static constexpr int G  = 64;   // C/2 groups
static constexpr int H  = 128;
static constexpr int W  = 128;
static constexpr int W2 = W / 2;             // 64 pixel-pairs per row
static constexpr long long TOTAL = (long long)B * G * H * W2;  // 8,388,608

__global__ __launch_bounds__(256)
void iwt_kernel(const float* __restrict__ x,
                const float* __restrict__ f,
                float* __restrict__ out)
{
    int idx = blockIdx.x * blockDim.x + threadIdx.x;   // < 2^23
    int w2 = idx & (W2 - 1);           // 0..63
    int h  = (idx >> 6) & (H - 1);     // 0..127
    int bg = idx >> 13;                // b*G + g, 0..1023

    // input: channel pair (2*bg, 2*bg+1); plane = H*W = 16384
    long long lo_off = (long long)(2 * bg) * (H * W) + h * W + 2 * w2;
    float2 lo = __ldg(reinterpret_cast<const float2*>(x + lo_off));
    float2 hi = __ldg(reinterpret_cast<const float2*>(x + lo_off + H * W));

    // filters: f[0..3] = f0 row-major, f[4..7] = f1 row-major
    float f00 = __ldg(f + 0), f01 = __ldg(f + 1);
    float f02 = __ldg(f + 2), f03 = __ldg(f + 3);
    float g00 = __ldg(f + 4), g01 = __ldg(f + 5);
    float g02 = __ldg(f + 6), g03 = __ldg(f + 7);

    // output: plane per (b,g) = 256*256; rows 2h / 2h+1, cols 4*w2..4*w2+3
    long long o_off = (long long)bg * (2 * H * 2 * W) + (2 * h) * (2 * W) + 4 * w2;

    float4 r0, r1;
    r0.x = fmaf(hi.x, g00, lo.x * f00);
    r0.y = fmaf(hi.x, g01, lo.x * f01);
    r0.z = fmaf(hi.y, g00, lo.y * f00);
    r0.w = fmaf(hi.y, g01, lo.y * f01);

    r1.x = fmaf(hi.x, g02, lo.x * f02);
    r1.y = fmaf(hi.x, g03, lo.x * f03);
    r1.z = fmaf(hi.y, g02, lo.y * f02);
    r1.w = fmaf(hi.y, g03, lo.y * f03);

    __stcs(reinterpret_cast<float4*>(out + o_off),         r0);
    __stcs(reinterpret_cast<float4*>(out + o_off + 2 * W), r1);
}

extern "C" void kernel_launch(void* const* d_in, const int* in_sizes, int n_in,
                              void* d_out, int out_size)
{
    const float* x = (const float*)d_in[0];
    const float* f = (const float*)d_in[1];
    float* out     = (float*)d_out;

    const int threads = 256;
    const int blocks  = (int)(TOTAL / threads);   // 32768, exact
    iwt_kernel<<<blocks, threads>>>(x, f, out);
}

// round 12
// speedup vs baseline: 1.0096x; 1.0096x over previous
#include <cuda_runtime.h>
#include <cuda_bf16.h>

// Inverse db1 DWT (Haar), grouped transposed conv 2x2 stride 2 — no overlap.
// x: (16, 128, 128, 128) f32; inv_filters: (2,2,2) f32
// out: (16, 64, 256, 256) f32
//
// out[b,g,2h+i,2w+j] = x[b,2g,h,w]*f0[i,j] + x[b,2g+1,h,w]*f1[i,j]
//
// R11: default cache policy everywhere (the R3/R5/R9/R10 lesson: write-back
// stores win on graph-replay steady state). 4 pixels per thread via float4
// loads; the 8-float output row span is ONE st.global.v8.f32 (sm_100+ 256-bit
// store) so every memory instruction is warp-dense:
//   loads:  32 lanes x 16 B = 512 B contiguous per channel
//   stores: 32 lanes x 32 B = 1024 B contiguous per output row

static constexpr int B  = 16;
static constexpr int G  = 64;    // C/2 groups
static constexpr int H  = 128;
static constexpr int W  = 128;
static constexpr int W4 = W / 4;             // 32 quads per input row
static constexpr long long TOTAL = (long long)B * G * H * W4;  // 4,194,304

__device__ __forceinline__ void stg_v8(float* p,
                                       float v0, float v1, float v2, float v3,
                                       float v4, float v5, float v6, float v7)
{
    asm volatile("st.global.v8.f32 [%0], {%1,%2,%3,%4,%5,%6,%7,%8};"
                 :: "l"(p), "f"(v0), "f"(v1), "f"(v2), "f"(v3),
                            "f"(v4), "f"(v5), "f"(v6), "f"(v7)
                 : "memory");
}

__global__ __launch_bounds__(256)
void iwt_kernel(const float* __restrict__ x,
                const float* __restrict__ f,
                float* __restrict__ out)
{
    int idx = blockIdx.x * blockDim.x + threadIdx.x;   // < 2^22
    int w4 = idx & (W4 - 1);           // 0..31 (lane-aligned)
    int h  = (idx >> 5) & (H - 1);     // 0..127
    int bg = idx >> 12;                // b*G + g, 0..1023

    // input: channel pair (2*bg, 2*bg+1); plane = H*W = 16384
    long long i_off = (long long)(2 * bg) * (H * W) + h * W + 4 * w4;
    float4 lo = *reinterpret_cast<const float4*>(x + i_off);
    float4 hi = *reinterpret_cast<const float4*>(x + i_off + H * W);

    // filters: f[0..3] = f0 row-major, f[4..7] = f1 row-major
    float f00 = __ldg(f + 0), f01 = __ldg(f + 1);
    float f02 = __ldg(f + 2), f03 = __ldg(f + 3);
    float g00 = __ldg(f + 4), g01 = __ldg(f + 5);
    float g02 = __ldg(f + 6), g03 = __ldg(f + 7);

    // output: plane per (b,g) = 256*256; rows 2h / 2h+1, cols 8*w4 .. 8*w4+7
    long long o_off = (long long)bg * (2 * H * 2 * W) + (2 * h) * (2 * W) + 8 * w4;
    float* o0 = out + o_off;
    float* o1 = o0 + 2 * W;

    // row 2h (filter row 0)
    stg_v8(o0,
           fmaf(hi.x, g00, lo.x * f00), fmaf(hi.x, g01, lo.x * f01),
           fmaf(hi.y, g00, lo.y * f00), fmaf(hi.y, g01, lo.y * f01),
           fmaf(hi.z, g00, lo.z * f00), fmaf(hi.z, g01, lo.z * f01),
           fmaf(hi.w, g00, lo.w * f00), fmaf(hi.w, g01, lo.w * f01));
    // row 2h+1 (filter row 1)
    stg_v8(o1,
           fmaf(hi.x, g02, lo.x * f02), fmaf(hi.x, g03, lo.x * f03),
           fmaf(hi.y, g02, lo.y * f02), fmaf(hi.y, g03, lo.y * f03),
           fmaf(hi.z, g02, lo.z * f02), fmaf(hi.z, g03, lo.z * f03),
           fmaf(hi.w, g02, lo.w * f02), fmaf(hi.w, g03, lo.w * f03));
}

extern "C" void kernel_launch(void* const* d_in, const int* in_sizes, int n_in,
                              void* d_out, int out_size)
{
    const float* x = (const float*)d_in[0];
    const float* f = (const float*)d_in[1];
    float* out     = (float*)d_out;

    const int threads = 256;
    const int blocks  = (int)(TOTAL / threads);   // 16384, exact
    iwt_kernel<<<blocks, threads>>>(x, f, out);
}